// round 15
// baseline (speedup 1.0000x reference)
#include <cuda_runtime.h>
#include <cuda_bf16.h>
#include <cstdint>
#include <math.h>

#define DINLINE static __device__ __forceinline__

// ---------------- problem dims ----------------
#define BATCH   16384
#define NCONT   13
#define EMB     128
#define NTAB    26
#define VOCAB   100000
#define K1      3456      // EMB*(1+NTAB)
#define N1      1024
#define N2      512
#define N3      256

// ---------------- scratch (device globals; no allocs allowed) ----------------
__device__ __nv_bfloat16 g_H0[(size_t)BATCH * K1];
__device__ __nv_bfloat16 g_H1[(size_t)BATCH * N1];
__device__ __nv_bfloat16 g_H2[(size_t)BATCH * N2];
__device__ __nv_bfloat16 g_H3[(size_t)BATCH * N3];
__device__ __nv_bfloat16 g_W1T[(size_t)N1 * K1];
__device__ __nv_bfloat16 g_W2T[(size_t)N2 * N1];
__device__ __nv_bfloat16 g_W3T[(size_t)N3 * N2];
__device__ int g_is64;

// ---------------- PTX helpers ----------------
DINLINE uint32_t smem_u32(const void* p) {
    uint32_t a;
    asm("{ .reg .u64 t; cvta.to.shared.u64 t, %1; cvt.u32.u64 %0, t; }" : "=r"(a) : "l"(p));
    return a;
}
DINLINE void cp_async16(uint32_t d, const void* s) {
    asm volatile("cp.async.cg.shared.global [%0], [%1], 16;" :: "r"(d), "l"(s));
}
DINLINE void cp_commit() { asm volatile("cp.async.commit_group;" ::: "memory"); }

DINLINE void ldmx4(uint32_t* r, uint32_t addr) {
    asm volatile("ldmatrix.sync.aligned.m8n8.x4.shared.b16 {%0,%1,%2,%3}, [%4];"
        : "=r"(r[0]), "=r"(r[1]), "=r"(r[2]), "=r"(r[3]) : "r"(addr));
}
DINLINE void mma16816(float* c, const uint32_t* a, uint32_t b0, uint32_t b1) {
    asm volatile("mma.sync.aligned.m16n8k16.row.col.f32.bf16.bf16.f32 "
        "{%0,%1,%2,%3}, {%4,%5,%6,%7}, {%8,%9}, {%0,%1,%2,%3};"
        : "+f"(c[0]), "+f"(c[1]), "+f"(c[2]), "+f"(c[3])
        : "r"(a[0]), "r"(a[1]), "r"(a[2]), "r"(a[3]), "r"(b0), "r"(b1));
}

// ---------------- weight transposes + int64-detect in ONE launch -------------
// fp32 [K,N] row-major -> bf16 [N,K] row-major. Last block: detect categorical
// dtype (odd 32-bit words all zero -> int64). Stream order puts this launch
// before prep_kernel, which reads g_is64.
#define TB1 ((N1/32)*(K1/32))   /* 3456 */
#define TB2 ((N2/32)*(N1/32))   /* 512  */
#define TB3 ((N3/32)*(N2/32))   /* 128  */
#define TBALL (TB1 + TB2 + TB3)
__global__ void transpose_all(const float* __restrict__ W1, const float* __restrict__ W2,
                              const float* __restrict__ W3,
                              const unsigned int* __restrict__ catw, int nwords) {
    int b = blockIdx.x;
    int t = threadIdx.y * 32 + threadIdx.x;
    if (b == TBALL) {
        __shared__ unsigned int red[256];
        unsigned int acc = 0;
        for (int i = 2 * t + 1; i < nwords; i += 512) acc |= catw[i];
        red[t] = acc;
        __syncthreads();
        for (int s = 128; s > 0; s >>= 1) {
            if (t < s) red[t] |= red[t + s];
            __syncthreads();
        }
        if (t == 0) g_is64 = (red[0] == 0u) ? 1 : 0;
        return;
    }
    __shared__ float tile[32][33];
    const float* in; __nv_bfloat16* out; int K, N;
    if (b < TB1)            { in = W1; out = g_W1T; K = K1; N = N1; }
    else if (b < TB1 + TB2) { b -= TB1; in = W2; out = g_W2T; K = N1; N = N2; }
    else                    { b -= TB1 + TB2; in = W3; out = g_W3T; K = N2; N = N3; }
    int nbk = N / 32;
    int nb = (b % nbk) * 32, kb = (b / nbk) * 32;
    #pragma unroll
    for (int i = threadIdx.y; i < 32; i += 8)
        tile[i][threadIdx.x] = in[(size_t)(kb + i) * N + nb + threadIdx.x];
    __syncthreads();
    #pragma unroll
    for (int i = threadIdx.y; i < 32; i += 8)
        out[(size_t)(nb + i) * K + kb + threadIdx.x] = __float2bfloat16(tile[threadIdx.x][i]);
}

// ---------------- dense bottom + embedding gather in one launch -------------
#define DENSE_BLOCKS (BATCH / 8)          /* 2048 */
#define GATHER_BLOCKS (BATCH * NTAB / 8)  /* 53248 */
__global__ void prep_kernel(const float* __restrict__ cont, const float* __restrict__ Wc,
                            const float* __restrict__ bc, const void* __restrict__ cat,
                            const float* __restrict__ tables) {
    int warp = threadIdx.x >> 5, lane = threadIdx.x & 31;
    if (blockIdx.x < DENSE_BLOCKS) {
        __shared__ float sW[NCONT * EMB];
        __shared__ float sbv[EMB];
        for (int i = threadIdx.x; i < NCONT * EMB; i += 256) sW[i] = Wc[i];
        if (threadIdx.x < EMB) sbv[threadIdx.x] = bc[threadIdx.x];
        __syncthreads();
        int b = blockIdx.x * 8 + warp;
        float cf[NCONT];
        #pragma unroll
        for (int i = 0; i < NCONT; i++) cf[i] = __ldg(cont + (size_t)b * NCONT + i);
        uint32_t pk[2];
        #pragma unroll
        for (int h = 0; h < 2; h++) {
            float v[2];
            #pragma unroll
            for (int q = 0; q < 2; q++) {
                int col = lane * 4 + h * 2 + q;
                float a = sbv[col];
                #pragma unroll
                for (int i = 0; i < NCONT; i++) a = fmaf(cf[i], sW[i * EMB + col], a);
                v[q] = a;
            }
            asm("cvt.rn.bf16x2.f32 %0, %1, %2;" : "=r"(pk[h]) : "f"(v[1]), "f"(v[0]));
        }
        ((uint2*)(g_H0 + (size_t)b * K1))[lane] = make_uint2(pk[0], pk[1]);
    } else {
        int gw = (blockIdx.x - DENSE_BLOCKS) * 8 + warp;
        int b = gw / NTAB, t = gw - b * NTAB;
        long long pos = (long long)b * NTAB + t;
        long long idx = g_is64 ? ((const long long*)cat)[pos]
                               : (long long)((const int*)cat)[pos];
        const float4* src = (const float4*)(tables + ((size_t)t * VOCAB + (size_t)idx) * EMB);
        float4 v = __ldg(src + lane);
        uint32_t lo, hi;
        asm("cvt.rn.bf16x2.f32 %0, %1, %2;" : "=r"(lo) : "f"(v.y), "f"(v.x));
        asm("cvt.rn.bf16x2.f32 %0, %1, %2;" : "=r"(hi) : "f"(v.w), "f"(v.z));
        ((uint2*)(g_H0 + (size_t)b * K1 + EMB + (size_t)t * EMB))[lane] = make_uint2(lo, hi);
    }
}

// ---------------- GEMM v9: C = relu(A @ Bw^T + bias) --------------------------
// R13 config (BM=128 BN=128 BK=64, 8 warps 4Mx2N, warp tile 32x64, 3-stage
// single-sync, 96KB smem, 2 CTAs/SM) with per-chunk scheduling fixes:
//  - kk=0's LDSMs issue immediately after the barrier (before the 16 volatile
//    cp.asyncs, which previously blocked them due to volatile-asm ordering)
//  - B fragments are LDSM'd one-ahead inside each kk.
#define STAGES  3
#define BM      128
#define BN      128
#define BK      64
#define GT      256
#define STG_B   ((BM + BN) * BK * 2)   /* 32768 */
#define B_OFF   (BM * BK * 2)          /* 16384 */
#define GEMM_SMEM (STAGES * STG_B)     /* 98304 -> 2 CTAs/SM */

// one kk-slice of the warp tile: LDSM A x2, B x4 (one-ahead) + 16 MMAs
DINLINE void chunk_kk(uint32_t st, uint32_t kb,
                      const uint32_t* aRowT, const uint32_t* aX,
                      const uint32_t* bRowT, const uint32_t* bX,
                      float acc[2][8][4]) {
    uint32_t a[2][4];
    ldmx4(a[0], st + aRowT[0] + (kb ^ aX[0]));
    ldmx4(a[1], st + aRowT[1] + (kb ^ aX[1]));
    uint32_t bf[2][4];
    ldmx4(bf[0], st + bRowT[0] + (kb ^ bX[0]));
    #pragma unroll
    for (int ni = 0; ni < 4; ni++) {
        int cur = ni & 1;
        if (ni < 3) ldmx4(bf[cur ^ 1], st + bRowT[ni + 1] + (kb ^ bX[ni + 1]));
        #pragma unroll
        for (int mi = 0; mi < 2; mi++) {
            mma16816(acc[mi][2 * ni],     a[mi], bf[cur][0], bf[cur][2]);
            mma16816(acc[mi][2 * ni + 1], a[mi], bf[cur][1], bf[cur][3]);
        }
    }
}

__global__ void __launch_bounds__(GT, 2)
gemm_bf16_relu(const __nv_bfloat16* __restrict__ A,
               const __nv_bfloat16* __restrict__ Bw,
               const float* __restrict__ bias,
               __nv_bfloat16* __restrict__ C,
               int Ntot, int Ktot) {
    extern __shared__ __align__(1024) char smem[];
    const uint32_t sbT = smem_u32(smem);
    const int tid = threadIdx.x, wid = tid >> 5, lane = tid & 31;
    const int ntn = Ntot / BN;
    const int mt = blockIdx.x / ntn, nt = blockIdx.x - mt * ntn;
    const int m0 = mt * BM, n0 = nt * BN;
    const int nch = Ktot / BK;
    const int wm = wid >> 1, wn = wid & 1;             // 4(M) x 2(N) warp grid
    const int g4 = lane >> 2, tg = lane & 3;
    const int lr = lane & 7, sel = lane >> 3;
    const int rowoff = ((sel & 1) << 3) + lr;
    const uint32_t koff2 = (uint32_t)(sel >> 1) << 4;

    // ---- loader: 8 x 16B granules per thread per chunk (4 A + 4 B at +32-row strides)
    const int r8 = tid >> 3, c8 = tid & 7;             // r8: 0..31
    const size_t stride32 = (size_t)32 * Ktot * 2;
    const char* srcA = (const char*)(A  + (size_t)(m0 + r8) * Ktot) + c8 * 16;
    const char* srcB = (const char*)(Bw + (size_t)(n0 + r8) * Ktot) + c8 * 16;
    uint32_t ba = (uint32_t)r8 * 128u + (uint32_t)c8 * 16u;
    const uint32_t dA = ba ^ ((ba >> 3) & 0x70u);      // SW128; invariant under +32 rows
    const uint32_t dB = B_OFF + dA;

    // ---- ldmatrix address precompute
    uint32_t aRowT[2], aX[2];
    #pragma unroll
    for (int mi = 0; mi < 2; mi++) {
        int row = wm * 32 + mi * 16 + rowoff;
        aRowT[mi] = (uint32_t)row * 128u;
        aX[mi]    = (uint32_t)(row & 7) << 4;
    }
    uint32_t bRowT[4], bX[4];
    #pragma unroll
    for (int ni = 0; ni < 4; ni++) {
        int row = wn * 64 + ni * 16 + rowoff;
        bRowT[ni] = B_OFF + (uint32_t)row * 128u;
        bX[ni]    = (uint32_t)(row & 7) << 4;
    }

    float acc[2][8][4];
    #pragma unroll
    for (int mi = 0; mi < 2; mi++)
        #pragma unroll
        for (int j = 0; j < 8; j++)
            #pragma unroll
            for (int q = 0; q < 4; q++) acc[mi][j][q] = 0.f;

    // ---- prologue: chunks 0..STAGES-2
    #pragma unroll
    for (int j = 0; j < STAGES - 1; j++) {
        uint32_t st = sbT + (uint32_t)j * STG_B;
        size_t ko = (size_t)j * (BK * 2);
        const char* pa = srcA + ko; const char* pb = srcB + ko;
        #pragma unroll
        for (int k = 0; k < 4; k++) cp_async16(st + dA + k * 4096u, pa + k * stride32);
        #pragma unroll
        for (int k = 0; k < 4; k++) cp_async16(st + dB + k * 4096u, pb + k * stride32);
        cp_commit();
    }

    int sw = STAGES - 1, sc = 0;
    for (int i = 0; i < nch; i++) {
        // chunk i's copies complete (for all threads once past the barrier)
        asm volatile("cp.async.wait_group 1;" ::: "memory");
        __syncthreads();

        uint32_t st = sbT + (uint32_t)sc * STG_B;
        if (++sc == STAGES) sc = 0;

        // kk=0 first: start the LDSM chain immediately after the barrier
        chunk_kk(st, koff2, aRowT, aX, bRowT, bX, acc);

        // issue chunk i+2 into stage sw (WAR safe: readers finished at iter i-1
        // and every warp passed the barrier above after that)
        int j = i + STAGES - 1;
        if (j < nch) {
            uint32_t stw = sbT + (uint32_t)sw * STG_B;
            size_t ko = (size_t)j * (BK * 2);
            const char* pa = srcA + ko; const char* pb = srcB + ko;
            #pragma unroll
            for (int k = 0; k < 4; k++) cp_async16(stw + dA + k * 4096u, pa + k * stride32);
            #pragma unroll
            for (int k = 0; k < 4; k++) cp_async16(stw + dB + k * 4096u, pb + k * stride32);
        }
        cp_commit();
        if (++sw == STAGES) sw = 0;

        // kk = 1..3
        #pragma unroll
        for (int kk = 1; kk < 4; kk++)
            chunk_kk(st, (uint32_t)(kk * 32) + koff2, aRowT, aX, bRowT, bX, acc);
    }

    // ---- epilogue: bias + relu + bf16 store
    #pragma unroll
    for (int mi = 0; mi < 2; mi++) {
        int row = m0 + wm * 32 + mi * 16 + g4;
        #pragma unroll
        for (int j = 0; j < 8; j++) {
            int col = n0 + wn * 64 + j * 8 + tg * 2;
            float bz0 = __ldg(bias + col), bz1 = __ldg(bias + col + 1);
            float v0 = fmaxf(acc[mi][j][0] + bz0, 0.f);
            float v1 = fmaxf(acc[mi][j][1] + bz1, 0.f);
            float v2 = fmaxf(acc[mi][j][2] + bz0, 0.f);
            float v3 = fmaxf(acc[mi][j][3] + bz1, 0.f);
            uint32_t p0, p1;
            asm("cvt.rn.bf16x2.f32 %0, %1, %2;" : "=r"(p0) : "f"(v1), "f"(v0));
            asm("cvt.rn.bf16x2.f32 %0, %1, %2;" : "=r"(p1) : "f"(v3), "f"(v2));
            *(uint32_t*)(C + (size_t)row * Ntot + col)       = p0;
            *(uint32_t*)(C + (size_t)(row + 8) * Ntot + col) = p1;
        }
    }
}

// Final: out[b] = sigmoid(H3[b,:] @ W_out + b_out)
__global__ void final_kernel(const __nv_bfloat16* __restrict__ H3, const float* __restrict__ Wo,
                             const float* __restrict__ bo, float* __restrict__ out) {
    __shared__ float sW[N3];
    if (threadIdx.x < N3) sW[threadIdx.x] = Wo[threadIdx.x];
    __syncthreads();
    int warp = threadIdx.x >> 5, lane = threadIdx.x & 31;
    int b = blockIdx.x * 8 + warp;
    uint4 v = __ldg((const uint4*)(H3 + (size_t)b * N3) + lane);
    uint32_t u[4] = {v.x, v.y, v.z, v.w};
    float acc = 0.f;
    #pragma unroll
    for (int j = 0; j < 4; j++) {
        __nv_bfloat162 h2 = *reinterpret_cast<__nv_bfloat162*>(&u[j]);
        acc += __bfloat162float(h2.x) * sW[lane * 8 + 2 * j];
        acc += __bfloat162float(h2.y) * sW[lane * 8 + 2 * j + 1];
    }
    #pragma unroll
    for (int s = 16; s > 0; s >>= 1) acc += __shfl_xor_sync(0xffffffffu, acc, s);
    if (lane == 0) out[b] = 1.f / (1.f + expf(-(acc + bo[0])));
}

// ---------------- launcher ----------------
extern "C" void kernel_launch(void* const* d_in, const int* in_sizes, int n_in,
                              void* d_out, int out_size) {
    (void)in_sizes; (void)n_in; (void)out_size;
    const float* cont = (const float*)d_in[0];
    const void*  cat  = d_in[1];
    const float* emb  = (const float*)d_in[2];
    const float* Wc   = (const float*)d_in[3];
    const float* bc   = (const float*)d_in[4];
    const float* W1   = (const float*)d_in[5];
    const float* b1   = (const float*)d_in[6];
    const float* W2   = (const float*)d_in[7];
    const float* b2   = (const float*)d_in[8];
    const float* W3   = (const float*)d_in[9];
    const float* b3   = (const float*)d_in[10];
    const float* Wo   = (const float*)d_in[11];
    const float* bo   = (const float*)d_in[12];
    float* out = (float*)d_out;

    void *h0, *h1, *h2, *h3, *w1t, *w2t, *w3t;
    cudaGetSymbolAddress(&h0,  g_H0);
    cudaGetSymbolAddress(&h1,  g_H1);
    cudaGetSymbolAddress(&h2,  g_H2);
    cudaGetSymbolAddress(&h3,  g_H3);
    cudaGetSymbolAddress(&w1t, g_W1T);
    cudaGetSymbolAddress(&w2t, g_W2T);
    cudaGetSymbolAddress(&w3t, g_W3T);

    cudaFuncSetAttribute(gemm_bf16_relu,
                         cudaFuncAttributeMaxDynamicSharedMemorySize, GEMM_SMEM);

    transpose_all<<<TBALL + 1, dim3(32, 8)>>>(W1, W2, W3,
                                              (const unsigned int*)cat, BATCH * NTAB);
    prep_kernel<<<DENSE_BLOCKS + GATHER_BLOCKS, 256>>>(cont, Wc, bc, cat, emb);

    gemm_bf16_relu<<<(BATCH / BM) * (N1 / BN), GT, GEMM_SMEM>>>(
        (const __nv_bfloat16*)h0, (const __nv_bfloat16*)w1t, b1,
        (__nv_bfloat16*)h1, N1, K1);
    gemm_bf16_relu<<<(BATCH / BM) * (N2 / BN), GT, GEMM_SMEM>>>(
        (const __nv_bfloat16*)h1, (const __nv_bfloat16*)w2t, b2,
        (__nv_bfloat16*)h2, N2, N1);
    gemm_bf16_relu<<<(BATCH / BM) * (N3 / BN), GT, GEMM_SMEM>>>(
        (const __nv_bfloat16*)h2, (const __nv_bfloat16*)w3t, b3,
        (__nv_bfloat16*)h3, N3, N2);

    final_kernel<<<BATCH / 8, 256>>>((const __nv_bfloat16*)h3, Wo, bo, out);
}

// round 16
// speedup vs baseline: 1.4364x; 1.4364x over previous
#include <cuda_runtime.h>
#include <cuda_bf16.h>
#include <cstdint>
#include <math.h>

#define DINLINE static __device__ __forceinline__

// ---------------- problem dims ----------------
#define BATCH   16384
#define NCONT   13
#define EMB     128
#define NTAB    26
#define VOCAB   100000
#define K1      3456      // EMB*(1+NTAB)
#define N1      1024
#define N2      512
#define N3      256

// ---------------- scratch (device globals; no allocs allowed) ----------------
__device__ __nv_bfloat16 g_H0[(size_t)BATCH * K1];
__device__ __nv_bfloat16 g_H1[(size_t)BATCH * N1];
__device__ __nv_bfloat16 g_H2[(size_t)BATCH * N2];
__device__ __nv_bfloat16 g_H3[(size_t)BATCH * N3];
__device__ __nv_bfloat16 g_W1T[(size_t)N1 * K1];
__device__ __nv_bfloat16 g_W2T[(size_t)N2 * N1];
__device__ __nv_bfloat16 g_W3T[(size_t)N3 * N2];
__device__ int g_is64;

// ---------------- PTX helpers ----------------
DINLINE uint32_t smem_u32(const void* p) {
    uint32_t a;
    asm("{ .reg .u64 t; cvta.to.shared.u64 t, %1; cvt.u32.u64 %0, t; }" : "=r"(a) : "l"(p));
    return a;
}
DINLINE void cp_async16(uint32_t d, const void* s) {
    asm volatile("cp.async.cg.shared.global [%0], [%1], 16;" :: "r"(d), "l"(s));
}
DINLINE void cp_commit() { asm volatile("cp.async.commit_group;" ::: "memory"); }

DINLINE void ldmx4(uint32_t* r, uint32_t addr) {
    asm volatile("ldmatrix.sync.aligned.m8n8.x4.shared.b16 {%0,%1,%2,%3}, [%4];"
        : "=r"(r[0]), "=r"(r[1]), "=r"(r[2]), "=r"(r[3]) : "r"(addr));
}
DINLINE void mma16816(float* c, const uint32_t* a, uint32_t b0, uint32_t b1) {
    asm volatile("mma.sync.aligned.m16n8k16.row.col.f32.bf16.bf16.f32 "
        "{%0,%1,%2,%3}, {%4,%5,%6,%7}, {%8,%9}, {%0,%1,%2,%3};"
        : "+f"(c[0]), "+f"(c[1]), "+f"(c[2]), "+f"(c[3])
        : "r"(a[0]), "r"(a[1]), "r"(a[2]), "r"(a[3]), "r"(b0), "r"(b1));
}

// ---------------- weight transposes + int64-detect in ONE launch -------------
#define TB1 ((N1/32)*(K1/32))   /* 3456 */
#define TB2 ((N2/32)*(N1/32))   /* 512  */
#define TB3 ((N3/32)*(N2/32))   /* 128  */
#define TBALL (TB1 + TB2 + TB3)
__global__ void transpose_all(const float* __restrict__ W1, const float* __restrict__ W2,
                              const float* __restrict__ W3,
                              const unsigned int* __restrict__ catw, int nwords) {
    int b = blockIdx.x;
    int t = threadIdx.y * 32 + threadIdx.x;
    if (b == TBALL) {
        __shared__ unsigned int red[256];
        unsigned int acc = 0;
        for (int i = 2 * t + 1; i < nwords; i += 512) acc |= catw[i];
        red[t] = acc;
        __syncthreads();
        for (int s = 128; s > 0; s >>= 1) {
            if (t < s) red[t] |= red[t + s];
            __syncthreads();
        }
        if (t == 0) g_is64 = (red[0] == 0u) ? 1 : 0;
        return;
    }
    __shared__ float tile[32][33];
    const float* in; __nv_bfloat16* out; int K, N;
    if (b < TB1)            { in = W1; out = g_W1T; K = K1; N = N1; }
    else if (b < TB1 + TB2) { b -= TB1; in = W2; out = g_W2T; K = N1; N = N2; }
    else                    { b -= TB1 + TB2; in = W3; out = g_W3T; K = N2; N = N3; }
    int nbk = N / 32;
    int nb = (b % nbk) * 32, kb = (b / nbk) * 32;
    #pragma unroll
    for (int i = threadIdx.y; i < 32; i += 8)
        tile[i][threadIdx.x] = in[(size_t)(kb + i) * N + nb + threadIdx.x];
    __syncthreads();
    #pragma unroll
    for (int i = threadIdx.y; i < 32; i += 8)
        out[(size_t)(nb + i) * K + kb + threadIdx.x] = __float2bfloat16(tile[threadIdx.x][i]);
}

// ---------------- dense bottom + embedding gather in one launch -------------
#define DENSE_BLOCKS (BATCH / 8)          /* 2048 */
#define GATHER_BLOCKS (BATCH * NTAB / 8)  /* 53248 */
__global__ void prep_kernel(const float* __restrict__ cont, const float* __restrict__ Wc,
                            const float* __restrict__ bc, const void* __restrict__ cat,
                            const float* __restrict__ tables) {
    int warp = threadIdx.x >> 5, lane = threadIdx.x & 31;
    if (blockIdx.x < DENSE_BLOCKS) {
        __shared__ float sW[NCONT * EMB];
        __shared__ float sbv[EMB];
        for (int i = threadIdx.x; i < NCONT * EMB; i += 256) sW[i] = Wc[i];
        if (threadIdx.x < EMB) sbv[threadIdx.x] = bc[threadIdx.x];
        __syncthreads();
        int b = blockIdx.x * 8 + warp;
        float cf[NCONT];
        #pragma unroll
        for (int i = 0; i < NCONT; i++) cf[i] = __ldg(cont + (size_t)b * NCONT + i);
        uint32_t pk[2];
        #pragma unroll
        for (int h = 0; h < 2; h++) {
            float v[2];
            #pragma unroll
            for (int q = 0; q < 2; q++) {
                int col = lane * 4 + h * 2 + q;
                float a = sbv[col];
                #pragma unroll
                for (int i = 0; i < NCONT; i++) a = fmaf(cf[i], sW[i * EMB + col], a);
                v[q] = a;
            }
            asm("cvt.rn.bf16x2.f32 %0, %1, %2;" : "=r"(pk[h]) : "f"(v[1]), "f"(v[0]));
        }
        ((uint2*)(g_H0 + (size_t)b * K1))[lane] = make_uint2(pk[0], pk[1]);
    } else {
        int gw = (blockIdx.x - DENSE_BLOCKS) * 8 + warp;
        int b = gw / NTAB, t = gw - b * NTAB;
        long long pos = (long long)b * NTAB + t;
        long long idx = g_is64 ? ((const long long*)cat)[pos]
                               : (long long)((const int*)cat)[pos];
        const float4* src = (const float4*)(tables + ((size_t)t * VOCAB + (size_t)idx) * EMB);
        float4 v = __ldg(src + lane);
        uint32_t lo, hi;
        asm("cvt.rn.bf16x2.f32 %0, %1, %2;" : "=r"(lo) : "f"(v.y), "f"(v.x));
        asm("cvt.rn.bf16x2.f32 %0, %1, %2;" : "=r"(hi) : "f"(v.w), "f"(v.z));
        ((uint2*)(g_H0 + (size_t)b * K1 + EMB + (size_t)t * EMB))[lane] = make_uint2(lo, hi);
    }
}

// ---------------- GEMM (R13 config, verbatim): C = relu(A @ Bw^T + bias) -----
// BM=128 BN=128 BK=64, 8 warps 4Mx2N, warp tile 32x64, 3-stage single-sync,
// 96KB smem -> 2 CTAs/SM, 121 regs. Measured best: tensor 65%, GEMM1 295us.
#define STAGES  3
#define BM      128
#define BN      128
#define BK      64
#define GT      256
#define STG_B   ((BM + BN) * BK * 2)   /* 32768 */
#define B_OFF   (BM * BK * 2)          /* 16384 */
#define GEMM_SMEM (STAGES * STG_B)     /* 98304 -> 2 CTAs/SM */

__global__ void __launch_bounds__(GT, 2)
gemm_bf16_relu(const __nv_bfloat16* __restrict__ A,
               const __nv_bfloat16* __restrict__ Bw,
               const float* __restrict__ bias,
               __nv_bfloat16* __restrict__ C,
               int Ntot, int Ktot) {
    extern __shared__ __align__(1024) char smem[];
    const uint32_t sbT = smem_u32(smem);
    const int tid = threadIdx.x, wid = tid >> 5, lane = tid & 31;
    const int ntn = Ntot / BN;
    const int mt = blockIdx.x / ntn, nt = blockIdx.x - mt * ntn;
    const int m0 = mt * BM, n0 = nt * BN;
    const int nch = Ktot / BK;
    const int wm = wid >> 1, wn = wid & 1;             // 4(M) x 2(N) warp grid
    const int g4 = lane >> 2, tg = lane & 3;
    const int lr = lane & 7, sel = lane >> 3;
    const int rowoff = ((sel & 1) << 3) + lr;
    const uint32_t koff2 = (uint32_t)(sel >> 1) << 4;

    // ---- loader: 8 x 16B granules per thread per chunk (4 A + 4 B at +32-row strides)
    const int r8 = tid >> 3, c8 = tid & 7;             // r8: 0..31
    const size_t stride32 = (size_t)32 * Ktot * 2;
    const char* srcA = (const char*)(A  + (size_t)(m0 + r8) * Ktot) + c8 * 16;
    const char* srcB = (const char*)(Bw + (size_t)(n0 + r8) * Ktot) + c8 * 16;
    uint32_t ba = (uint32_t)r8 * 128u + (uint32_t)c8 * 16u;
    const uint32_t dA = ba ^ ((ba >> 3) & 0x70u);      // SW128; invariant under +32 rows
    const uint32_t dB = B_OFF + dA;

    // ---- ldmatrix address precompute
    uint32_t aRowT[2], aX[2];
    #pragma unroll
    for (int mi = 0; mi < 2; mi++) {
        int row = wm * 32 + mi * 16 + rowoff;
        aRowT[mi] = (uint32_t)row * 128u;
        aX[mi]    = (uint32_t)(row & 7) << 4;
    }
    uint32_t bRowT[4], bX[4];
    #pragma unroll
    for (int ni = 0; ni < 4; ni++) {
        int row = wn * 64 + ni * 16 + rowoff;
        bRowT[ni] = B_OFF + (uint32_t)row * 128u;
        bX[ni]    = (uint32_t)(row & 7) << 4;
    }

    float acc[2][8][4];
    #pragma unroll
    for (int mi = 0; mi < 2; mi++)
        #pragma unroll
        for (int j = 0; j < 8; j++)
            #pragma unroll
            for (int q = 0; q < 4; q++) acc[mi][j][q] = 0.f;

    // ---- prologue: chunks 0..STAGES-2
    #pragma unroll
    for (int j = 0; j < STAGES - 1; j++) {
        uint32_t st = sbT + (uint32_t)j * STG_B;
        size_t ko = (size_t)j * (BK * 2);
        const char* pa = srcA + ko; const char* pb = srcB + ko;
        #pragma unroll
        for (int k = 0; k < 4; k++) cp_async16(st + dA + k * 4096u, pa + k * stride32);
        #pragma unroll
        for (int k = 0; k < 4; k++) cp_async16(st + dB + k * 4096u, pb + k * stride32);
        cp_commit();
    }

    int sw = STAGES - 1, sc = 0;
    for (int i = 0; i < nch; i++) {
        // chunk i's copies complete (for all threads once past the barrier)
        asm volatile("cp.async.wait_group 1;" ::: "memory");
        __syncthreads();

        // issue chunk i+2 into stage sw (WAR safe: readers of sw finished at
        // iter i-1 and every warp passed the barrier above after that)
        int j = i + STAGES - 1;
        if (j < nch) {
            uint32_t st = sbT + (uint32_t)sw * STG_B;
            size_t ko = (size_t)j * (BK * 2);
            const char* pa = srcA + ko; const char* pb = srcB + ko;
            #pragma unroll
            for (int k = 0; k < 4; k++) cp_async16(st + dA + k * 4096u, pa + k * stride32);
            #pragma unroll
            for (int k = 0; k < 4; k++) cp_async16(st + dB + k * 4096u, pb + k * stride32);
        }
        cp_commit();
        if (++sw == STAGES) sw = 0;

        uint32_t st = sbT + (uint32_t)sc * STG_B;
        if (++sc == STAGES) sc = 0;
        #pragma unroll
        for (int kk = 0; kk < 4; kk++) {
            uint32_t kb = (uint32_t)(kk * 32) + koff2;
            uint32_t a[2][4];
            #pragma unroll
            for (int mi = 0; mi < 2; mi++)
                ldmx4(a[mi], st + aRowT[mi] + (kb ^ aX[mi]));
            #pragma unroll
            for (int ni = 0; ni < 4; ni++) {
                uint32_t bf[4];
                ldmx4(bf, st + bRowT[ni] + (kb ^ bX[ni]));
                #pragma unroll
                for (int mi = 0; mi < 2; mi++) {
                    mma16816(acc[mi][2 * ni],     a[mi], bf[0], bf[2]);
                    mma16816(acc[mi][2 * ni + 1], a[mi], bf[1], bf[3]);
                }
            }
        }
    }

    // ---- epilogue: bias + relu + bf16 store
    #pragma unroll
    for (int mi = 0; mi < 2; mi++) {
        int row = m0 + wm * 32 + mi * 16 + g4;
        #pragma unroll
        for (int j = 0; j < 8; j++) {
            int col = n0 + wn * 64 + j * 8 + tg * 2;
            float bz0 = __ldg(bias + col), bz1 = __ldg(bias + col + 1);
            float v0 = fmaxf(acc[mi][j][0] + bz0, 0.f);
            float v1 = fmaxf(acc[mi][j][1] + bz1, 0.f);
            float v2 = fmaxf(acc[mi][j][2] + bz0, 0.f);
            float v3 = fmaxf(acc[mi][j][3] + bz1, 0.f);
            uint32_t p0, p1;
            asm("cvt.rn.bf16x2.f32 %0, %1, %2;" : "=r"(p0) : "f"(v1), "f"(v0));
            asm("cvt.rn.bf16x2.f32 %0, %1, %2;" : "=r"(p1) : "f"(v3), "f"(v2));
            *(uint32_t*)(C + (size_t)row * Ntot + col)       = p0;
            *(uint32_t*)(C + (size_t)(row + 8) * Ntot + col) = p1;
        }
    }
}

// Final: out[b] = sigmoid(H3[b,:] @ W_out + b_out)
__global__ void final_kernel(const __nv_bfloat16* __restrict__ H3, const float* __restrict__ Wo,
                             const float* __restrict__ bo, float* __restrict__ out) {
    __shared__ float sW[N3];
    if (threadIdx.x < N3) sW[threadIdx.x] = Wo[threadIdx.x];
    __syncthreads();
    int warp = threadIdx.x >> 5, lane = threadIdx.x & 31;
    int b = blockIdx.x * 8 + warp;
    uint4 v = __ldg((const uint4*)(H3 + (size_t)b * N3) + lane);
    uint32_t u[4] = {v.x, v.y, v.z, v.w};
    float acc = 0.f;
    #pragma unroll
    for (int j = 0; j < 4; j++) {
        __nv_bfloat162 h2 = *reinterpret_cast<__nv_bfloat162*>(&u[j]);
        acc += __bfloat162float(h2.x) * sW[lane * 8 + 2 * j];
        acc += __bfloat162float(h2.y) * sW[lane * 8 + 2 * j + 1];
    }
    #pragma unroll
    for (int s = 16; s > 0; s >>= 1) acc += __shfl_xor_sync(0xffffffffu, acc, s);
    if (lane == 0) out[b] = 1.f / (1.f + expf(-(acc + bo[0])));
}

// ---------------- launcher ----------------
extern "C" void kernel_launch(void* const* d_in, const int* in_sizes, int n_in,
                              void* d_out, int out_size) {
    (void)in_sizes; (void)n_in; (void)out_size;
    const float* cont = (const float*)d_in[0];
    const void*  cat  = d_in[1];
    const float* emb  = (const float*)d_in[2];
    const float* Wc   = (const float*)d_in[3];
    const float* bc   = (const float*)d_in[4];
    const float* W1   = (const float*)d_in[5];
    const float* b1   = (const float*)d_in[6];
    const float* W2   = (const float*)d_in[7];
    const float* b2   = (const float*)d_in[8];
    const float* W3   = (const float*)d_in[9];
    const float* b3   = (const float*)d_in[10];
    const float* Wo   = (const float*)d_in[11];
    const float* bo   = (const float*)d_in[12];
    float* out = (float*)d_out;

    void *h0, *h1, *h2, *h3, *w1t, *w2t, *w3t;
    cudaGetSymbolAddress(&h0,  g_H0);
    cudaGetSymbolAddress(&h1,  g_H1);
    cudaGetSymbolAddress(&h2,  g_H2);
    cudaGetSymbolAddress(&h3,  g_H3);
    cudaGetSymbolAddress(&w1t, g_W1T);
    cudaGetSymbolAddress(&w2t, g_W2T);
    cudaGetSymbolAddress(&w3t, g_W3T);

    cudaFuncSetAttribute(gemm_bf16_relu,
                         cudaFuncAttributeMaxDynamicSharedMemorySize, GEMM_SMEM);

    transpose_all<<<TBALL + 1, dim3(32, 8)>>>(W1, W2, W3,
                                              (const unsigned int*)cat, BATCH * NTAB);
    prep_kernel<<<DENSE_BLOCKS + GATHER_BLOCKS, 256>>>(cont, Wc, bc, cat, emb);

    gemm_bf16_relu<<<(BATCH / BM) * (N1 / BN), GT, GEMM_SMEM>>>(
        (const __nv_bfloat16*)h0, (const __nv_bfloat16*)w1t, b1,
        (__nv_bfloat16*)h1, N1, K1);
    gemm_bf16_relu<<<(BATCH / BM) * (N2 / BN), GT, GEMM_SMEM>>>(
        (const __nv_bfloat16*)h1, (const __nv_bfloat16*)w2t, b2,
        (__nv_bfloat16*)h2, N2, N1);
    gemm_bf16_relu<<<(BATCH / BM) * (N3 / BN), GT, GEMM_SMEM>>>(
        (const __nv_bfloat16*)h2, (const __nv_bfloat16*)w3t, b3,
        (__nv_bfloat16*)h3, N3, N2);

    final_kernel<<<BATCH / 8, 256>>>((const __nv_bfloat16*)h3, Wo, bo, out);
}